// round 15
// baseline (speedup 1.0000x reference)
#include <cuda_runtime.h>
#include <cuda_fp16.h>
#include <math.h>

#define TCNT 4
#define CH 3
#define HH 128
#define WW 128
#define PSZ 5
#define KSEL 14
#define WSZ 29
#define WHALF 14
#define PADT 16
#define XPH 160
#define XPW 160
#define TX 32
#define TY 8
#define NOFF (WSZ*WSZ)
#define NGRP ((NOFF + 3) / 4)     /* 211 groups of 4 offsets */
#define NRANK 4
#define NRG 4                     /* gather ranks per tile */
#define DFEAT 75
#define NPIX (TCNT*HH*WW)
#define PLANE NPIX

// k_dist dynamic smem layout (bytes)
#define SM_PX     0                      /* u64[40*64]       = 20480 */
#define SM_E      20480                  /* half2[4][432]    = 6912  */
#define SM_H      (20480 + 6912)         /* half2[2][8][36]  = 2304  */
#define SM_TOTAL  (20480 + 6912 + 2304)  /* 29696 */

typedef unsigned long long u64;

// ---------------- device scratch (no allocations allowed) ----------------
__device__ float  g_mean[TCNT*CH];
__device__ float  g_beta;
__device__ float4 g_xp[TCNT*XPH*XPW];          // normalized, mean-sub, reflect-padded; c in .x/.y/.z
__device__ float  g_pdeno[DFEAT*PLANE];        // plane-major [d][t][H][W]
__device__ unsigned g_keys[NRANK*KSEL*NPIX];   // per-rank per-pixel sorted top-K keys, plane-major
__device__ __align__(16) unsigned g_ordw[NGRP*4];  // ring-ordered, pre-decoded: (off_lin<<16)|raster

// ---------------- prep: per (t,c) mean + beta (blocks 0-11), ring order (blocks 12-15) ----------------
__global__ void k_prep(const float* __restrict__ noisy, const int* __restrict__ sigp) {
    if (blockIdx.x >= 12) {
        int o = (blockIdx.x - 12) * 256 + threadIdx.x;
        if (o >= NOFF) return;
        int oy = o / WSZ, ox = o - (o/WSZ)*WSZ;
        int dy = oy - WHALF, dx = ox - WHALF;
        int ady = dy < 0 ? -dy : dy, adx = dx < 0 ? -dx : dx;
        int rr = ady > adx ? ady : adx;
        int before = (rr == 0) ? 0 : (2*rr-1)*(2*rr-1);
        int cnt = 0;
        for (int yy = WHALF - rr; yy < oy; yy++) {
            int a = yy - WHALF; a = a < 0 ? -a : a;
            cnt += (a == rr) ? (2*rr + 1) : 2;
        }
        if (ady == rr) cnt += dx + rr;
        else          cnt += (dx == rr) ? 1 : 0;
        g_ordw[before + cnt] = (((unsigned)oy * 64u + (unsigned)ox) << 16)
                             | ((unsigned)oy * (unsigned)WSZ + (unsigned)ox);
        return;
    }
    if (blockIdx.x == 0 && threadIdx.x == 0) {
        unsigned bits = *(const unsigned*)sigp;
        float sv = (bits >> 23) ? __uint_as_float(bits) : (float)(int)bits;
        float sig = sv / 127.5f;
        g_beta = 1.0f / (2.0f * sig * sig * (float)DFEAT);
    }
    int b = blockIdx.x;   // t*3+c
    const float* p = noisy + (size_t)b * (HH*WW);
    float s = 0.f;
    for (int i = threadIdx.x; i < HH*WW; i += 256) s += p[i];
    __shared__ float sm[8];
    #pragma unroll
    for (int off = 16; off; off >>= 1) s += __shfl_down_sync(0xffffffffu, s, off);
    if ((threadIdx.x & 31) == 0) sm[threadIdx.x >> 5] = s;
    __syncthreads();
    if (threadIdx.x == 0) {
        float tot = 0.f;
        #pragma unroll
        for (int i = 0; i < 8; i++) tot += sm[i];
        g_mean[b] = tot * (1.0f/(HH*WW)) * (1.0f/127.5f) - 1.0f;
    }
}

// ---------------- build padded normalized image (float4 per pixel) ----------------
__global__ void k_xp(const float* __restrict__ noisy) {
    int idx = blockIdx.x * 256 + threadIdx.x;       // over t*XPH*XPW
    if (idx >= TCNT*XPH*XPW) return;
    int ix = idx % XPW;
    int r  = idx / XPW;
    int iy = r % XPH;
    int t  = r / XPH;
    int jy = iy - PADT; jy = jy < 0 ? -jy : (jy > HH-1 ? 2*(HH-1)-jy : jy);
    int jx = ix - PADT; jx = jx < 0 ? -jx : (jx > WW-1 ? 2*(WW-1)-jx : jx);
    const float* base = noisy + (size_t)t * CH * HH * WW;
    float4 v;
    v.x = base[(size_t)(0*HH+jy)*WW + jx] * (1.f/127.5f) - 1.f - g_mean[t*3+0];
    v.y = base[(size_t)(1*HH+jy)*WW + jx] * (1.f/127.5f) - 1.f - g_mean[t*3+1];
    v.z = base[(size_t)(2*HH+jy)*WW + jx] * (1.f/127.5f) - 1.f - g_mean[t*3+2];
    v.w = 0.f;
    g_xp[idx] = v;
}

// ---------------- distance kernel (fp16): quarter of the ring per CTA ----------------
__global__ void __launch_bounds__(256, 4) k_dist() {
    extern __shared__ unsigned char smem_raw[];
    u64*     rpx  = (u64*)(smem_raw + SM_PX);      // [40*64] packed halves {x,y,z,0}
    __half2* e_sm = (__half2*)(smem_raw + SM_E);   // [4][432] (2 offsets per half2)
    __half2* hbuf = (__half2*)(smem_raw + SM_H);   // [2][8][36]

    int rank = blockIdx.x & (NRANK - 1);
    int t    = blockIdx.z;
    int ty0  = blockIdx.y * TY;
    int tx0  = (blockIdx.x >> 2) * TX;
    int tid  = threadIdx.x;

    // stage region, converted to packed fp16
    const float4* xp = g_xp + (size_t)t * XPH * XPW;
    #pragma unroll
    for (int i = tid; i < 40*64; i += 256) {
        int r = i >> 6, c = i & 63;
        float4 v = xp[(size_t)(ty0 + r) * XPW + tx0 + c];
        __half2 xy = __floats2half2_rn(v.x, v.y);
        __half2 z0 = __floats2half2_rn(v.z, 0.f);
        unsigned lo = *reinterpret_cast<unsigned*>(&xy);
        unsigned hi = *reinterpret_cast<unsigned*>(&z0);
        rpx[i] = ((u64)hi << 32) | (u64)lo;
    }
    __syncthreads();

    auto ldpx = [&](int idx, __half2& xy, __half2& z0) {
        u64 n = rpx[idx];
        unsigned lo = (unsigned)n, hi = (unsigned)(n >> 32);
        xy = *reinterpret_cast<__half2*>(&lo);
        z0 = *reinterpret_cast<__half2*>(&hi);
    };

    // register-cached query pixels for the e-plane (slots tid and tid+256)
    int er1 = tid / 36, ec1 = tid - er1 * 36;
    int it2 = tid + 256;
    int er2 = it2 / 36, ec2 = it2 - er2 * 36;       // valid when tid < 176
    __half2 q1xy, q1z0, q2xy, q2z0;
    ldpx((er1 + 14) * 64 + (ec1 + 14), q1xy, q1z0);
    if (tid < 176) ldpx((er2 + 14) * 64 + (ec2 + 14), q2xy, q2z0);
    else { q2xy = __float2half2_rn(0.f); q2z0 = __float2half2_rn(0.f); }
    int nb1 = er1 * 64 + ec1;
    int nb2 = er2 * 64 + ec2;

    int ly = tid >> 5, l = tid & 31;

    unsigned keys[KSEL];
    #pragma unroll
    for (int i = 0; i < KSEL; i++) keys[i] = 0xFFFFFFFFu;

    auto esq = [&](int idx, __half2 qxy, __half2 qz0) -> __half {
        __half2 nxy, nz0; ldpx(idx, nxy, nz0);
        __half2 dxy = __hsub2(qxy, nxy);
        __half2 dz0 = __hsub2(qz0, nz0);
        __half2 s   = __hfma2(dxy, dxy, __hmul2(dz0, dz0));
        return __hadd(__low2half(s), __high2half(s));
    };

    auto fillG = [&](__half2* pA, __half2* pB, uint4 gw) {
        int o0 = (int)(gw.x >> 16), o1 = (int)(gw.y >> 16);
        int o2 = (int)(gw.z >> 16), o3 = (int)(gw.w >> 16);
        {
            __half e0 = esq(nb1 + o0, q1xy, q1z0);
            __half e1 = esq(nb1 + o1, q1xy, q1z0);
            __half e2 = esq(nb1 + o2, q1xy, q1z0);
            __half e3 = esq(nb1 + o3, q1xy, q1z0);
            pA[tid] = __halves2half2(e0, e1);
            pB[tid] = __halves2half2(e2, e3);
        }
        if (tid < 176) {
            __half e0 = esq(nb2 + o0, q2xy, q2z0);
            __half e1 = esq(nb2 + o1, q2xy, q2z0);
            __half e2 = esq(nb2 + o2, q2xy, q2z0);
            __half e3 = esq(nb2 + o3, q2xy, q2z0);
            pA[it2] = __halves2half2(e0, e1);
            pB[it2] = __halves2half2(e2, e3);
        }
    };

    auto ins1 = [&](unsigned k) {
        if (__any_sync(0xffffffffu, k < keys[KSEL-1])) {
            #pragma unroll
            for (int s = KSEL-1; s >= 1; s--) keys[s] = umin(keys[s], umax(keys[s-1], k));
            keys[0] = umin(keys[0], k);
        }
    };

    auto bcG = [&](const __half2* pA, const __half2* pB, uint4 gw, bool kill123) {
        const __half2* rA = pA + ly * 36;
        const __half2* rB = pB + ly * 36;
        __half2* hA = hbuf + (size_t)ly * 36;
        __half2* hB = hbuf + (size_t)(8 + ly) * 36;
        __half2 vaA = __hadd2(__hadd2(__hadd2(rA[l], rA[36+l]), __hadd2(rA[72+l], rA[108+l])), rA[144+l]);
        __half2 vaB = __hadd2(__hadd2(__hadd2(rB[l], rB[36+l]), __hadd2(rB[72+l], rB[108+l])), rB[144+l]);
        hA[l] = vaA;
        hB[l] = vaB;
        if (l < 4) {
            int c2 = 32 + l;
            __half2 vbA = __hadd2(__hadd2(__hadd2(rA[c2], rA[36+c2]), __hadd2(rA[72+c2], rA[108+c2])), rA[144+c2]);
            __half2 vbB = __hadd2(__hadd2(__hadd2(rB[c2], rB[36+c2]), __hadd2(rB[72+c2], rB[108+c2])), rB[144+c2]);
            hA[32 + l] = vbA;
            hB[32 + l] = vbB;
        }
        __syncwarp(0xffffffffu);
        __half2 dA = __hadd2(__hadd2(__hadd2(hA[l], hA[l+1]), __hadd2(hA[l+2], hA[l+3])), hA[l+4]);
        __half2 dB = __hadd2(__hadd2(__hadd2(hB[l], hB[l+1]), __hadd2(hB[l+2], hB[l+3])), hB[l+4]);
        unsigned bA = *reinterpret_cast<unsigned*>(&dA);
        unsigned bB = *reinterpret_cast<unsigned*>(&dB);
        unsigned k0 = ((bA & 0xFFFFu) << 10) | (gw.x & 0x3FFu);
        unsigned k1 = ((bA >> 16)    << 10) | (gw.y & 0x3FFu);
        unsigned k2 = ((bB & 0xFFFFu) << 10) | (gw.z & 0x3FFu);
        unsigned k3 = ((bB >> 16)    << 10) | (gw.w & 0x3FFu);
        if (kill123) { k1 = 0xFFFFFFFFu; k2 = 0xFFFFFFFFu; k3 = 0xFFFFFFFFu; }
        unsigned mn = umin(umin(k0, k1), umin(k2, k3));
        if (__any_sync(0xffffffffu, mn < keys[KSEL-1])) {
            ins1(k0); ins1(k1); ins1(k2); ins1(k3);
        }
    };

    const uint4* ordp = (const uint4*)g_ordw;
    auto loadg = [&](int g) -> uint4 {
        uint4 v = ordp[g];
        if (g == NGRP - 1) { v.y = v.x; v.z = v.x; v.w = v.x; }
        return v;
    };

    // this CTA handles groups g = rank, rank+4, ... (interleaved ring order)
    int ng = (NGRP - rank + NRANK - 1) / NRANK;
    uint4 w_cur = loadg(rank);
    fillG(e_sm, e_sm + 432, w_cur);
    uint4 w_nxt = (ng > 1) ? loadg(rank + NRANK) : make_uint4(0,0,0,0);

    #pragma unroll 2
    for (int i = 0; i < ng; i++) {
        int side = i & 1;
        __syncthreads();
        if (i + 1 < ng) {
            __half2* p2 = e_sm + (size_t)((side ^ 1) << 1) * 432;
            fillG(p2, p2 + 432, w_nxt);
        }
        uint4 w_n2 = (i + 2 < ng) ? loadg(rank + NRANK*(i + 2)) : make_uint4(0,0,0,0);
        __half2* pc = e_sm + (size_t)(side << 1) * 432;
        bcG(pc, pc + 432, w_cur, (rank + NRANK*i) == NGRP - 1);
        w_cur = w_nxt; w_nxt = w_n2;
    }

    size_t pix = ((size_t)t * HH + (ty0 + ly)) * WW + (tx0 + l);
    #pragma unroll
    for (int i = 0; i < KSEL; i++)
        g_keys[(size_t)(rank * KSEL + i) * NPIX + pix] = keys[i];
}

// ---------------- gather helper: compile-time range of patch positions ----------------
template<int PB, int PE>
__device__ __forceinline__ void gather_part(const float4* __restrict__ reg4,
                                            const float* __restrict__ w,
                                            const int* __restrict__ olin,
                                            float* __restrict__ pd, int base_px) {
    #pragma unroll
    for (int p = PB; p < PE; p++) {
        int dy = p / PSZ, dx = p - (p / PSZ) * PSZ;
        float ax = 0.f, ay = 0.f, az = 0.f;
        int bb = base_px + dy * 64 + dx;
        #pragma unroll
        for (int k = 0; k < KSEL; k++) {
            float4 v = reg4[bb + olin[k]];
            ax += w[k] * v.x;
            ay += w[k] * v.y;
            az += w[k] * v.z;
        }
        pd[(size_t)(p * 3 + 0) * PLANE] = ax;
        pd[(size_t)(p * 3 + 1) * PLANE] = ay;
        pd[(size_t)(p * 3 + 2) * PLANE] = az;
    }
}

// ---------------- merge + softmax + patch gather (fp32), 4 ranks over patch positions ----------------
__global__ void __launch_bounds__(256, 3) k_gath() {
    __shared__ float4 reg4[40*64];

    int rank = blockIdx.x & (NRG - 1);
    int t    = blockIdx.z;
    int ty0  = blockIdx.y * TY;
    int tx0  = (blockIdx.x >> 2) * TX;
    int tid  = threadIdx.x;
    int ly = tid >> 5, l = tid & 31;

    const float4* xp = g_xp + (size_t)t * XPH * XPW;
    #pragma unroll
    for (int i = tid; i < 40*64; i += 256) {
        int r = i >> 6, c = i & 63;
        reg4[i] = xp[(size_t)(ty0 + r) * XPW + tx0 + c];
    }

    size_t pix = ((size_t)t * HH + (ty0 + ly)) * WW + (tx0 + l);

    // merge rank-0 list with ranks 1..3 (preload per rank, insert with early break)
    unsigned keys[KSEL];
    #pragma unroll
    for (int i = 0; i < KSEL; i++) keys[i] = g_keys[(size_t)i * NPIX + pix];
    #pragma unroll
    for (int r = 1; r < NRANK; r++) {
        unsigned rk[KSEL];
        #pragma unroll
        for (int j = 0; j < KSEL; j++) rk[j] = g_keys[(size_t)(r * KSEL + j) * NPIX + pix];
        #pragma unroll
        for (int j = 0; j < KSEL; j++) {
            unsigned k = rk[j];
            if (k >= keys[KSEL-1]) break;           // rank list sorted ascending
            #pragma unroll
            for (int s = KSEL-1; s >= 1; s--) keys[s] = umin(keys[s], umax(keys[s-1], k));
            keys[0] = umin(keys[0], k);
        }
    }

    // softmax over fp16-coded distances
    float w[KSEL];
    int   olin[KSEL];
    float beta = g_beta;
    __half h0 = __ushort_as_half((unsigned short)((keys[0] >> 10) & 0xFFFFu));
    float d0 = __half2float(h0);
    float ssum = 0.f;
    #pragma unroll
    for (int i = 0; i < KSEL; i++) {
        __half hi = __ushort_as_half((unsigned short)((keys[i] >> 10) & 0xFFFFu));
        float di = __half2float(hi);
        float wi = expf(beta * (d0 - di));
        w[i] = wi; ssum += wi;
        int o  = (int)(keys[i] & 0x3FFu);
        int oyk = o / WSZ;
        int oxk = o - oyk * WSZ;
        olin[i] = oyk * 64 + oxk;
    }
    float inv = 1.0f / ssum;
    #pragma unroll
    for (int i = 0; i < KSEL; i++) w[i] *= inv;

    __syncthreads();   // region staged (merge/softmax overlapped the staging loads)

    // this rank's slice of the 25 patch positions (disjoint pdeno planes)
    float* pd = g_pdeno + (long long)pix;
    int base_px = ly * 64 + l;
    if      (rank == 0) gather_part<0, 7 >(reg4, w, olin, pd, base_px);
    else if (rank == 1) gather_part<7, 13>(reg4, w, olin, pd, base_px);
    else if (rank == 2) gather_part<13,19>(reg4, w, olin, pd, base_px);
    else                gather_part<19,25>(reg4, w, olin, pd, base_px);
}

// ---------------- fold + denormalize ----------------
__global__ void k_fold(float* __restrict__ out) {
    int idx = blockIdx.x * 256 + threadIdx.x;        // over t*c*H*W
    if (idx >= TCNT*CH*HH*WW) return;
    int x = idx & 127;
    int r = idx >> 7;
    int y = r & 127;
    r >>= 7;
    int c = r % 3;
    int t = r / 3;
    float s = 0.f;
    int n = 0;
    #pragma unroll
    for (int py = 0; py < PSZ; py++) {
        int yy = y + 2 - py;
        if (yy < 0 || yy > HH-1) continue;
        #pragma unroll
        for (int px = 0; px < PSZ; px++) {
            int xx = x + 2 - px;
            if (xx < 0 || xx > WW-1) continue;
            int p = (py * PSZ + px) * 3 + c;
            s += g_pdeno[(size_t)p * PLANE + ((size_t)t * HH + yy) * WW + xx];
            n++;
        }
    }
    out[idx] = 127.5f * (s / (float)n + g_mean[t*3+c] + 1.0f);
}

// ---------------- launch ----------------
extern "C" void kernel_launch(void* const* d_in, const int* in_sizes, int n_in,
                              void* d_out, int out_size) {
    const float* noisy = (const float*)d_in[0];
    const int*   sigp  = (const int*)d_in[1];
    float*       out   = (float*)d_out;

    cudaFuncSetAttribute(k_dist, cudaFuncAttributeMaxDynamicSharedMemorySize, SM_TOTAL);
    cudaFuncSetAttribute(k_dist, cudaFuncAttributePreferredSharedMemoryCarveout,
                         cudaSharedmemCarveoutMaxShared);
    cudaFuncSetAttribute(k_gath, cudaFuncAttributePreferredSharedMemoryCarveout,
                         cudaSharedmemCarveoutMaxShared);

    k_prep<<<16, 256>>>(noisy, sigp);                  // means+beta (0-11) + ring order (12-15)
    k_xp<<<(TCNT*XPH*XPW + 255)/256, 256>>>(noisy);
    dim3 gridD(NRANK * (WW/TX), HH/TY, TCNT);          // 1024 CTAs: 4 ranks per tile
    k_dist<<<gridD, 256, SM_TOTAL>>>();
    dim3 gridG(NRG * (WW/TX), HH/TY, TCNT);            // 1024 CTAs: 4 gather ranks per tile
    k_gath<<<gridG, 256>>>();
    k_fold<<<(TCNT*CH*HH*WW + 255)/256, 256>>>(out);
}

// round 16
// speedup vs baseline: 1.0237x; 1.0237x over previous
#include <cuda_runtime.h>
#include <cuda_fp16.h>
#include <math.h>

#define TCNT 4
#define CH 3
#define HH 128
#define WW 128
#define PSZ 5
#define KSEL 14
#define WSZ 29
#define WHALF 14
#define PADT 16
#define XPH 160
#define XPW 160
#define TX 32
#define TY 8
#define TYG 4                     /* gather tile height */
#define NOFF (WSZ*WSZ)
#define NGRP ((NOFF + 3) / 4)     /* 211 groups of 4 offsets */
#define NRANK 4
#define DFEAT 75
#define NPIX (TCNT*HH*WW)
#define PLANE NPIX

// k_dist dynamic smem layout (bytes)
#define SM_PX     0                      /* u64[40*64]       = 20480 */
#define SM_E      20480                  /* half2[4][432]    = 6912  */
#define SM_H      (20480 + 6912)         /* half2[2][8][36]  = 2304  */
#define SM_TOTAL  (20480 + 6912 + 2304)  /* 29696 */

typedef unsigned long long u64;

// ---------------- device scratch (no allocations allowed) ----------------
__device__ float  g_mean[TCNT*CH];
__device__ float  g_beta;
__device__ float4 g_xp[TCNT*XPH*XPW];          // normalized, mean-sub, reflect-padded; c in .x/.y/.z
__device__ float  g_pdeno[DFEAT*PLANE];        // plane-major [d][t][H][W]
__device__ unsigned g_keys[NRANK*KSEL*NPIX];   // per-rank per-pixel sorted top-K keys, plane-major
__device__ __align__(16) unsigned g_ordw[NGRP*4];  // ring-ordered, pre-decoded: (off_lin<<16)|raster

// ---------------- prep: per (t,c) mean + beta (blocks 0-11), ring order (blocks 12-15) ----------------
__global__ void k_prep(const float* __restrict__ noisy, const int* __restrict__ sigp) {
    if (blockIdx.x >= 12) {
        int o = (blockIdx.x - 12) * 256 + threadIdx.x;
        if (o >= NOFF) return;
        int oy = o / WSZ, ox = o - (o/WSZ)*WSZ;
        int dy = oy - WHALF, dx = ox - WHALF;
        int ady = dy < 0 ? -dy : dy, adx = dx < 0 ? -dx : dx;
        int rr = ady > adx ? ady : adx;
        int before = (rr == 0) ? 0 : (2*rr-1)*(2*rr-1);
        int cnt = 0;
        for (int yy = WHALF - rr; yy < oy; yy++) {
            int a = yy - WHALF; a = a < 0 ? -a : a;
            cnt += (a == rr) ? (2*rr + 1) : 2;
        }
        if (ady == rr) cnt += dx + rr;
        else          cnt += (dx == rr) ? 1 : 0;
        g_ordw[before + cnt] = (((unsigned)oy * 64u + (unsigned)ox) << 16)
                             | ((unsigned)oy * (unsigned)WSZ + (unsigned)ox);
        return;
    }
    if (blockIdx.x == 0 && threadIdx.x == 0) {
        unsigned bits = *(const unsigned*)sigp;
        float sv = (bits >> 23) ? __uint_as_float(bits) : (float)(int)bits;
        float sig = sv / 127.5f;
        g_beta = 1.0f / (2.0f * sig * sig * (float)DFEAT);
    }
    int b = blockIdx.x;   // t*3+c
    const float* p = noisy + (size_t)b * (HH*WW);
    float s = 0.f;
    for (int i = threadIdx.x; i < HH*WW; i += 256) s += p[i];
    __shared__ float sm[8];
    #pragma unroll
    for (int off = 16; off; off >>= 1) s += __shfl_down_sync(0xffffffffu, s, off);
    if ((threadIdx.x & 31) == 0) sm[threadIdx.x >> 5] = s;
    __syncthreads();
    if (threadIdx.x == 0) {
        float tot = 0.f;
        #pragma unroll
        for (int i = 0; i < 8; i++) tot += sm[i];
        g_mean[b] = tot * (1.0f/(HH*WW)) * (1.0f/127.5f) - 1.0f;
    }
}

// ---------------- build padded normalized image (float4 per pixel) ----------------
__global__ void k_xp(const float* __restrict__ noisy) {
    int idx = blockIdx.x * 256 + threadIdx.x;       // over t*XPH*XPW
    if (idx >= TCNT*XPH*XPW) return;
    int ix = idx % XPW;
    int r  = idx / XPW;
    int iy = r % XPH;
    int t  = r / XPH;
    int jy = iy - PADT; jy = jy < 0 ? -jy : (jy > HH-1 ? 2*(HH-1)-jy : jy);
    int jx = ix - PADT; jx = jx < 0 ? -jx : (jx > WW-1 ? 2*(WW-1)-jx : jx);
    const float* base = noisy + (size_t)t * CH * HH * WW;
    float4 v;
    v.x = base[(size_t)(0*HH+jy)*WW + jx] * (1.f/127.5f) - 1.f - g_mean[t*3+0];
    v.y = base[(size_t)(1*HH+jy)*WW + jx] * (1.f/127.5f) - 1.f - g_mean[t*3+1];
    v.z = base[(size_t)(2*HH+jy)*WW + jx] * (1.f/127.5f) - 1.f - g_mean[t*3+2];
    v.w = 0.f;
    g_xp[idx] = v;
}

// ---------------- distance kernel (fp16): quarter of the ring per CTA ----------------
__global__ void __launch_bounds__(256, 4) k_dist() {
    extern __shared__ unsigned char smem_raw[];
    u64*     rpx  = (u64*)(smem_raw + SM_PX);      // [40*64] packed halves {x,y,z,0}
    __half2* e_sm = (__half2*)(smem_raw + SM_E);   // [4][432] (2 offsets per half2)
    __half2* hbuf = (__half2*)(smem_raw + SM_H);   // [2][8][36]

    int rank = blockIdx.x & (NRANK - 1);
    int t    = blockIdx.z;
    int ty0  = blockIdx.y * TY;
    int tx0  = (blockIdx.x >> 2) * TX;
    int tid  = threadIdx.x;

    // stage region, converted to packed fp16
    const float4* xp = g_xp + (size_t)t * XPH * XPW;
    #pragma unroll
    for (int i = tid; i < 40*64; i += 256) {
        int r = i >> 6, c = i & 63;
        float4 v = xp[(size_t)(ty0 + r) * XPW + tx0 + c];
        __half2 xy = __floats2half2_rn(v.x, v.y);
        __half2 z0 = __floats2half2_rn(v.z, 0.f);
        unsigned lo = *reinterpret_cast<unsigned*>(&xy);
        unsigned hi = *reinterpret_cast<unsigned*>(&z0);
        rpx[i] = ((u64)hi << 32) | (u64)lo;
    }
    __syncthreads();

    auto ldpx = [&](int idx, __half2& xy, __half2& z0) {
        u64 n = rpx[idx];
        unsigned lo = (unsigned)n, hi = (unsigned)(n >> 32);
        xy = *reinterpret_cast<__half2*>(&lo);
        z0 = *reinterpret_cast<__half2*>(&hi);
    };

    // register-cached query pixels for the e-plane (slots tid and tid+256)
    int er1 = tid / 36, ec1 = tid - er1 * 36;
    int it2 = tid + 256;
    int er2 = it2 / 36, ec2 = it2 - er2 * 36;       // valid when tid < 176
    __half2 q1xy, q1z0, q2xy, q2z0;
    ldpx((er1 + 14) * 64 + (ec1 + 14), q1xy, q1z0);
    if (tid < 176) ldpx((er2 + 14) * 64 + (ec2 + 14), q2xy, q2z0);
    else { q2xy = __float2half2_rn(0.f); q2z0 = __float2half2_rn(0.f); }
    int nb1 = er1 * 64 + ec1;
    int nb2 = er2 * 64 + ec2;

    int ly = tid >> 5, l = tid & 31;

    unsigned keys[KSEL];
    #pragma unroll
    for (int i = 0; i < KSEL; i++) keys[i] = 0xFFFFFFFFu;

    auto esq = [&](int idx, __half2 qxy, __half2 qz0) -> __half {
        __half2 nxy, nz0; ldpx(idx, nxy, nz0);
        __half2 dxy = __hsub2(qxy, nxy);
        __half2 dz0 = __hsub2(qz0, nz0);
        __half2 s   = __hfma2(dxy, dxy, __hmul2(dz0, dz0));
        return __hadd(__low2half(s), __high2half(s));
    };

    auto fillG = [&](__half2* pA, __half2* pB, uint4 gw) {
        int o0 = (int)(gw.x >> 16), o1 = (int)(gw.y >> 16);
        int o2 = (int)(gw.z >> 16), o3 = (int)(gw.w >> 16);
        {
            __half e0 = esq(nb1 + o0, q1xy, q1z0);
            __half e1 = esq(nb1 + o1, q1xy, q1z0);
            __half e2 = esq(nb1 + o2, q1xy, q1z0);
            __half e3 = esq(nb1 + o3, q1xy, q1z0);
            pA[tid] = __halves2half2(e0, e1);
            pB[tid] = __halves2half2(e2, e3);
        }
        if (tid < 176) {
            __half e0 = esq(nb2 + o0, q2xy, q2z0);
            __half e1 = esq(nb2 + o1, q2xy, q2z0);
            __half e2 = esq(nb2 + o2, q2xy, q2z0);
            __half e3 = esq(nb2 + o3, q2xy, q2z0);
            pA[it2] = __halves2half2(e0, e1);
            pB[it2] = __halves2half2(e2, e3);
        }
    };

    auto ins1 = [&](unsigned k) {
        if (__any_sync(0xffffffffu, k < keys[KSEL-1])) {
            #pragma unroll
            for (int s = KSEL-1; s >= 1; s--) keys[s] = umin(keys[s], umax(keys[s-1], k));
            keys[0] = umin(keys[0], k);
        }
    };

    auto bcG = [&](const __half2* pA, const __half2* pB, uint4 gw, bool kill123) {
        const __half2* rA = pA + ly * 36;
        const __half2* rB = pB + ly * 36;
        __half2* hA = hbuf + (size_t)ly * 36;
        __half2* hB = hbuf + (size_t)(8 + ly) * 36;
        __half2 vaA = __hadd2(__hadd2(__hadd2(rA[l], rA[36+l]), __hadd2(rA[72+l], rA[108+l])), rA[144+l]);
        __half2 vaB = __hadd2(__hadd2(__hadd2(rB[l], rB[36+l]), __hadd2(rB[72+l], rB[108+l])), rB[144+l]);
        hA[l] = vaA;
        hB[l] = vaB;
        if (l < 4) {
            int c2 = 32 + l;
            __half2 vbA = __hadd2(__hadd2(__hadd2(rA[c2], rA[36+c2]), __hadd2(rA[72+c2], rA[108+c2])), rA[144+c2]);
            __half2 vbB = __hadd2(__hadd2(__hadd2(rB[c2], rB[36+c2]), __hadd2(rB[72+c2], rB[108+c2])), rB[144+c2]);
            hA[32 + l] = vbA;
            hB[32 + l] = vbB;
        }
        __syncwarp(0xffffffffu);
        __half2 dA = __hadd2(__hadd2(__hadd2(hA[l], hA[l+1]), __hadd2(hA[l+2], hA[l+3])), hA[l+4]);
        __half2 dB = __hadd2(__hadd2(__hadd2(hB[l], hB[l+1]), __hadd2(hB[l+2], hB[l+3])), hB[l+4]);
        unsigned bA = *reinterpret_cast<unsigned*>(&dA);
        unsigned bB = *reinterpret_cast<unsigned*>(&dB);
        unsigned k0 = ((bA & 0xFFFFu) << 10) | (gw.x & 0x3FFu);
        unsigned k1 = ((bA >> 16)    << 10) | (gw.y & 0x3FFu);
        unsigned k2 = ((bB & 0xFFFFu) << 10) | (gw.z & 0x3FFu);
        unsigned k3 = ((bB >> 16)    << 10) | (gw.w & 0x3FFu);
        if (kill123) { k1 = 0xFFFFFFFFu; k2 = 0xFFFFFFFFu; k3 = 0xFFFFFFFFu; }
        unsigned mn = umin(umin(k0, k1), umin(k2, k3));
        if (__any_sync(0xffffffffu, mn < keys[KSEL-1])) {
            ins1(k0); ins1(k1); ins1(k2); ins1(k3);
        }
    };

    const uint4* ordp = (const uint4*)g_ordw;
    auto loadg = [&](int g) -> uint4 {
        uint4 v = ordp[g];
        if (g == NGRP - 1) { v.y = v.x; v.z = v.x; v.w = v.x; }
        return v;
    };

    // this CTA handles groups g = rank, rank+4, ... (interleaved ring order)
    int ng = (NGRP - rank + NRANK - 1) / NRANK;
    uint4 w_cur = loadg(rank);
    fillG(e_sm, e_sm + 432, w_cur);
    uint4 w_nxt = (ng > 1) ? loadg(rank + NRANK) : make_uint4(0,0,0,0);

    #pragma unroll 2
    for (int i = 0; i < ng; i++) {
        int side = i & 1;
        __syncthreads();
        if (i + 1 < ng) {
            __half2* p2 = e_sm + (size_t)((side ^ 1) << 1) * 432;
            fillG(p2, p2 + 432, w_nxt);
        }
        uint4 w_n2 = (i + 2 < ng) ? loadg(rank + NRANK*(i + 2)) : make_uint4(0,0,0,0);
        __half2* pc = e_sm + (size_t)(side << 1) * 432;
        bcG(pc, pc + 432, w_cur, (rank + NRANK*i) == NGRP - 1);
        w_cur = w_nxt; w_nxt = w_n2;
    }

    size_t pix = ((size_t)t * HH + (ty0 + ly)) * WW + (tx0 + l);
    #pragma unroll
    for (int i = 0; i < KSEL; i++)
        g_keys[(size_t)(rank * KSEL + i) * NPIX + pix] = keys[i];
}

// ---------------- gather helper: compile-time range of patch positions ----------------
template<int PB, int PE>
__device__ __forceinline__ void gather_part(const float4* __restrict__ reg4,
                                            const float* __restrict__ w,
                                            const int* __restrict__ olin,
                                            float* __restrict__ pd, int base_px) {
    #pragma unroll
    for (int p = PB; p < PE; p++) {
        int dy = p / PSZ, dx = p - (p / PSZ) * PSZ;
        float ax = 0.f, ay = 0.f, az = 0.f;
        int bb = base_px + dy * 64 + dx;
        #pragma unroll
        for (int k = 0; k < KSEL; k++) {
            float4 v = reg4[bb + olin[k]];
            ax += w[k] * v.x;
            ay += w[k] * v.y;
            az += w[k] * v.z;
        }
        pd[(size_t)(p * 3 + 0) * PLANE] = ax;
        pd[(size_t)(p * 3 + 1) * PLANE] = ay;
        pd[(size_t)(p * 3 + 2) * PLANE] = az;
    }
}

// ---------------- merge + softmax + patch gather: 32x4 tiles, 2 threads/pixel ----------------
__global__ void __launch_bounds__(256, 3) k_gath() {
    __shared__ float4 reg4[36*64];     // rows ty0..ty0+35 (TYG=4: ly+dy+oyk <= 3+4+28 = 35)

    int t   = blockIdx.z;
    int ty0 = blockIdx.y * TYG;
    int tx0 = blockIdx.x * TX;
    int tid = threadIdx.x;
    int pi   = tid & 127;              // pixel index within 32x4 tile
    int half = tid >> 7;               // 0: positions 0-12, 1: positions 13-24
    int ly = pi >> 5, l = pi & 31;

    const float4* xp = g_xp + (size_t)t * XPH * XPW;
    #pragma unroll
    for (int i = tid; i < 36*64; i += 256) {
        int r = i >> 6, c = i & 63;
        reg4[i] = xp[(size_t)(ty0 + r) * XPW + tx0 + c];
    }

    size_t pix = ((size_t)t * HH + (ty0 + ly)) * WW + (tx0 + l);

    // merge rank-0 list with ranks 1..3 (preload per rank, insert with early break)
    unsigned keys[KSEL];
    #pragma unroll
    for (int i = 0; i < KSEL; i++) keys[i] = g_keys[(size_t)i * NPIX + pix];
    #pragma unroll
    for (int r = 1; r < NRANK; r++) {
        unsigned rk[KSEL];
        #pragma unroll
        for (int j = 0; j < KSEL; j++) rk[j] = g_keys[(size_t)(r * KSEL + j) * NPIX + pix];
        #pragma unroll
        for (int j = 0; j < KSEL; j++) {
            unsigned k = rk[j];
            if (k >= keys[KSEL-1]) break;           // rank list sorted ascending
            #pragma unroll
            for (int s = KSEL-1; s >= 1; s--) keys[s] = umin(keys[s], umax(keys[s-1], k));
            keys[0] = umin(keys[0], k);
        }
    }

    // softmax over fp16-coded distances
    float w[KSEL];
    int   olin[KSEL];
    float beta = g_beta;
    __half h0 = __ushort_as_half((unsigned short)((keys[0] >> 10) & 0xFFFFu));
    float d0 = __half2float(h0);
    float ssum = 0.f;
    #pragma unroll
    for (int i = 0; i < KSEL; i++) {
        __half hi = __ushort_as_half((unsigned short)((keys[i] >> 10) & 0xFFFFu));
        float di = __half2float(hi);
        float wi = expf(beta * (d0 - di));
        w[i] = wi; ssum += wi;
        int o  = (int)(keys[i] & 0x3FFu);
        int oyk = o / WSZ;
        int oxk = o - oyk * WSZ;
        olin[i] = oyk * 64 + oxk;
    }
    float inv = 1.0f / ssum;
    #pragma unroll
    for (int i = 0; i < KSEL; i++) w[i] *= inv;

    __syncthreads();   // region staged (merge/softmax overlapped the staging loads)

    // this thread's half of the 25 patch positions (disjoint pdeno planes)
    float* pd = g_pdeno + (long long)pix;
    int base_px = ly * 64 + l;
    if (half == 0) gather_part<0, 13>(reg4, w, olin, pd, base_px);
    else           gather_part<13, 25>(reg4, w, olin, pd, base_px);
}

// ---------------- fold + denormalize ----------------
__global__ void k_fold(float* __restrict__ out) {
    int idx = blockIdx.x * 256 + threadIdx.x;        // over t*c*H*W
    if (idx >= TCNT*CH*HH*WW) return;
    int x = idx & 127;
    int r = idx >> 7;
    int y = r & 127;
    r >>= 7;
    int c = r % 3;
    int t = r / 3;
    float s = 0.f;
    int n = 0;
    #pragma unroll
    for (int py = 0; py < PSZ; py++) {
        int yy = y + 2 - py;
        if (yy < 0 || yy > HH-1) continue;
        #pragma unroll
        for (int px = 0; px < PSZ; px++) {
            int xx = x + 2 - px;
            if (xx < 0 || xx > WW-1) continue;
            int p = (py * PSZ + px) * 3 + c;
            s += g_pdeno[(size_t)p * PLANE + ((size_t)t * HH + yy) * WW + xx];
            n++;
        }
    }
    out[idx] = 127.5f * (s / (float)n + g_mean[t*3+c] + 1.0f);
}

// ---------------- launch ----------------
extern "C" void kernel_launch(void* const* d_in, const int* in_sizes, int n_in,
                              void* d_out, int out_size) {
    const float* noisy = (const float*)d_in[0];
    const int*   sigp  = (const int*)d_in[1];
    float*       out   = (float*)d_out;

    cudaFuncSetAttribute(k_dist, cudaFuncAttributeMaxDynamicSharedMemorySize, SM_TOTAL);
    cudaFuncSetAttribute(k_dist, cudaFuncAttributePreferredSharedMemoryCarveout,
                         cudaSharedmemCarveoutMaxShared);
    cudaFuncSetAttribute(k_gath, cudaFuncAttributePreferredSharedMemoryCarveout,
                         cudaSharedmemCarveoutMaxShared);

    k_prep<<<16, 256>>>(noisy, sigp);                  // means+beta (0-11) + ring order (12-15)
    k_xp<<<(TCNT*XPH*XPW + 255)/256, 256>>>(noisy);
    dim3 gridD(NRANK * (WW/TX), HH/TY, TCNT);          // 1024 CTAs: 4 ranks per tile
    k_dist<<<gridD, 256, SM_TOTAL>>>();
    dim3 gridG(WW/TX, HH/TYG, TCNT);                   // 512 CTAs: 32x4 tiles
    k_gath<<<gridG, 256>>>();
    k_fold<<<(TCNT*CH*HH*WW + 255)/256, 256>>>(out);
}

// round 17
// speedup vs baseline: 1.1146x; 1.0887x over previous
#include <cuda_runtime.h>
#include <cuda_fp16.h>
#include <math.h>

#define TCNT 4
#define CH 3
#define HH 128
#define WW 128
#define PSZ 5
#define KSEL 14
#define WSZ 29
#define WHALF 14
#define PADT 16
#define XPH 160
#define XPW 160
#define TX 32
#define TY 8
#define TYG 4                     /* gather tile height */
#define NOFF (WSZ*WSZ)
#define NGRP ((NOFF + 3) / 4)     /* 211 groups of 4 offsets */
#define NRANK 4
#define DFEAT 75
#define NPIX (TCNT*HH*WW)
#define PLANE NPIX

// k_dist dynamic smem layout (bytes)
#define SM_PX     0                      /* u64[40*64]       = 20480 */
#define SM_E      20480                  /* half2[4][432]    = 6912  */
#define SM_H      (20480 + 6912)         /* half2[2][8][36]  = 2304  */
#define SM_TOTAL  (20480 + 6912 + 2304)  /* 29696 */

typedef unsigned long long u64;

// ---------------- device scratch (no allocations allowed) ----------------
__device__ float  g_mean[TCNT*CH];
__device__ float  g_beta;
__device__ float4 g_xp[TCNT*XPH*XPW];          // normalized, mean-sub, reflect-padded; c in .x/.y/.z
__device__ float  g_pdeno[DFEAT*PLANE];        // plane-major [d][t][H][W]
__device__ unsigned g_keys[NRANK*KSEL*NPIX];   // per-rank per-pixel sorted top-K keys, plane-major
__device__ __align__(16) unsigned g_ordw[NGRP*4];  // ring-ordered, pre-decoded: (off_lin<<16)|raster

// ---------------- prep: per (t,c) mean + beta (blocks 0-11), ring order (blocks 12-15) ----------------
__global__ void k_prep(const float* __restrict__ noisy, const int* __restrict__ sigp) {
    if (blockIdx.x >= 12) {
        int o = (blockIdx.x - 12) * 256 + threadIdx.x;
        if (o >= NOFF) return;
        int oy = o / WSZ, ox = o - (o/WSZ)*WSZ;
        int dy = oy - WHALF, dx = ox - WHALF;
        int ady = dy < 0 ? -dy : dy, adx = dx < 0 ? -dx : dx;
        int rr = ady > adx ? ady : adx;
        int before = (rr == 0) ? 0 : (2*rr-1)*(2*rr-1);
        int cnt = 0;
        for (int yy = WHALF - rr; yy < oy; yy++) {
            int a = yy - WHALF; a = a < 0 ? -a : a;
            cnt += (a == rr) ? (2*rr + 1) : 2;
        }
        if (ady == rr) cnt += dx + rr;
        else          cnt += (dx == rr) ? 1 : 0;
        g_ordw[before + cnt] = (((unsigned)oy * 64u + (unsigned)ox) << 16)
                             | ((unsigned)oy * (unsigned)WSZ + (unsigned)ox);
        return;
    }
    if (blockIdx.x == 0 && threadIdx.x == 0) {
        unsigned bits = *(const unsigned*)sigp;
        float sv = (bits >> 23) ? __uint_as_float(bits) : (float)(int)bits;
        float sig = sv / 127.5f;
        g_beta = 1.0f / (2.0f * sig * sig * (float)DFEAT);
    }
    int b = blockIdx.x;   // t*3+c
    const float* p = noisy + (size_t)b * (HH*WW);
    float s = 0.f;
    for (int i = threadIdx.x; i < HH*WW; i += 256) s += p[i];
    __shared__ float sm[8];
    #pragma unroll
    for (int off = 16; off; off >>= 1) s += __shfl_down_sync(0xffffffffu, s, off);
    if ((threadIdx.x & 31) == 0) sm[threadIdx.x >> 5] = s;
    __syncthreads();
    if (threadIdx.x == 0) {
        float tot = 0.f;
        #pragma unroll
        for (int i = 0; i < 8; i++) tot += sm[i];
        g_mean[b] = tot * (1.0f/(HH*WW)) * (1.0f/127.5f) - 1.0f;
    }
}

// ---------------- build padded normalized image (float4 per pixel) ----------------
__global__ void k_xp(const float* __restrict__ noisy) {
    int idx = blockIdx.x * 256 + threadIdx.x;       // over t*XPH*XPW
    if (idx >= TCNT*XPH*XPW) return;
    int ix = idx % XPW;
    int r  = idx / XPW;
    int iy = r % XPH;
    int t  = r / XPH;
    int jy = iy - PADT; jy = jy < 0 ? -jy : (jy > HH-1 ? 2*(HH-1)-jy : jy);
    int jx = ix - PADT; jx = jx < 0 ? -jx : (jx > WW-1 ? 2*(WW-1)-jx : jx);
    const float* base = noisy + (size_t)t * CH * HH * WW;
    float4 v;
    v.x = base[(size_t)(0*HH+jy)*WW + jx] * (1.f/127.5f) - 1.f - g_mean[t*3+0];
    v.y = base[(size_t)(1*HH+jy)*WW + jx] * (1.f/127.5f) - 1.f - g_mean[t*3+1];
    v.z = base[(size_t)(2*HH+jy)*WW + jx] * (1.f/127.5f) - 1.f - g_mean[t*3+2];
    v.w = 0.f;
    g_xp[idx] = v;
}

// ---------------- distance kernel (fp16): quarter of the ring per CTA ----------------
__global__ void __launch_bounds__(256, 4) k_dist() {
    extern __shared__ unsigned char smem_raw[];
    u64*     rpx  = (u64*)(smem_raw + SM_PX);      // [40*64] packed halves {x,y,z,0}
    __half2* e_sm = (__half2*)(smem_raw + SM_E);   // [4][432] (2 offsets per half2)
    __half2* hbuf = (__half2*)(smem_raw + SM_H);   // [2][8][36]

    int rank = blockIdx.x & (NRANK - 1);
    int t    = blockIdx.z;
    int ty0  = blockIdx.y * TY;
    int tx0  = (blockIdx.x >> 2) * TX;
    int tid  = threadIdx.x;

    // stage region, converted to packed fp16
    const float4* xp = g_xp + (size_t)t * XPH * XPW;
    #pragma unroll
    for (int i = tid; i < 40*64; i += 256) {
        int r = i >> 6, c = i & 63;
        float4 v = xp[(size_t)(ty0 + r) * XPW + tx0 + c];
        __half2 xy = __floats2half2_rn(v.x, v.y);
        __half2 z0 = __floats2half2_rn(v.z, 0.f);
        unsigned lo = *reinterpret_cast<unsigned*>(&xy);
        unsigned hi = *reinterpret_cast<unsigned*>(&z0);
        rpx[i] = ((u64)hi << 32) | (u64)lo;
    }
    __syncthreads();

    auto ldpx = [&](int idx, __half2& xy, __half2& z0) {
        u64 n = rpx[idx];
        unsigned lo = (unsigned)n, hi = (unsigned)(n >> 32);
        xy = *reinterpret_cast<__half2*>(&lo);
        z0 = *reinterpret_cast<__half2*>(&hi);
    };

    // register-cached query pixels for the e-plane (slots tid and tid+256)
    int er1 = tid / 36, ec1 = tid - er1 * 36;
    int it2 = tid + 256;
    int er2 = it2 / 36, ec2 = it2 - er2 * 36;       // valid when tid < 176
    __half2 q1xy, q1z0, q2xy, q2z0;
    ldpx((er1 + 14) * 64 + (ec1 + 14), q1xy, q1z0);
    if (tid < 176) ldpx((er2 + 14) * 64 + (ec2 + 14), q2xy, q2z0);
    else { q2xy = __float2half2_rn(0.f); q2z0 = __float2half2_rn(0.f); }
    int nb1 = er1 * 64 + ec1;
    int nb2 = er2 * 64 + ec2;

    int ly = tid >> 5, l = tid & 31;

    unsigned keys[KSEL];
    #pragma unroll
    for (int i = 0; i < KSEL; i++) keys[i] = 0xFFFFFFFFu;

    auto esq = [&](int idx, __half2 qxy, __half2 qz0) -> __half {
        __half2 nxy, nz0; ldpx(idx, nxy, nz0);
        __half2 dxy = __hsub2(qxy, nxy);
        __half2 dz0 = __hsub2(qz0, nz0);
        __half2 s   = __hfma2(dxy, dxy, __hmul2(dz0, dz0));
        return __hadd(__low2half(s), __high2half(s));
    };

    auto fillG = [&](__half2* pA, __half2* pB, uint4 gw) {
        int o0 = (int)(gw.x >> 16), o1 = (int)(gw.y >> 16);
        int o2 = (int)(gw.z >> 16), o3 = (int)(gw.w >> 16);
        {
            __half e0 = esq(nb1 + o0, q1xy, q1z0);
            __half e1 = esq(nb1 + o1, q1xy, q1z0);
            __half e2 = esq(nb1 + o2, q1xy, q1z0);
            __half e3 = esq(nb1 + o3, q1xy, q1z0);
            pA[tid] = __halves2half2(e0, e1);
            pB[tid] = __halves2half2(e2, e3);
        }
        if (tid < 176) {
            __half e0 = esq(nb2 + o0, q2xy, q2z0);
            __half e1 = esq(nb2 + o1, q2xy, q2z0);
            __half e2 = esq(nb2 + o2, q2xy, q2z0);
            __half e3 = esq(nb2 + o3, q2xy, q2z0);
            pA[it2] = __halves2half2(e0, e1);
            pB[it2] = __halves2half2(e2, e3);
        }
    };

    auto ins1 = [&](unsigned k) {
        if (__any_sync(0xffffffffu, k < keys[KSEL-1])) {
            #pragma unroll
            for (int s = KSEL-1; s >= 1; s--) keys[s] = umin(keys[s], umax(keys[s-1], k));
            keys[0] = umin(keys[0], k);
        }
    };

    auto bcG = [&](const __half2* pA, const __half2* pB, uint4 gw, bool kill123) {
        const __half2* rA = pA + ly * 36;
        const __half2* rB = pB + ly * 36;
        __half2* hA = hbuf + (size_t)ly * 36;
        __half2* hB = hbuf + (size_t)(8 + ly) * 36;
        __half2 vaA = __hadd2(__hadd2(__hadd2(rA[l], rA[36+l]), __hadd2(rA[72+l], rA[108+l])), rA[144+l]);
        __half2 vaB = __hadd2(__hadd2(__hadd2(rB[l], rB[36+l]), __hadd2(rB[72+l], rB[108+l])), rB[144+l]);
        hA[l] = vaA;
        hB[l] = vaB;
        if (l < 4) {
            int c2 = 32 + l;
            __half2 vbA = __hadd2(__hadd2(__hadd2(rA[c2], rA[36+c2]), __hadd2(rA[72+c2], rA[108+c2])), rA[144+c2]);
            __half2 vbB = __hadd2(__hadd2(__hadd2(rB[c2], rB[36+c2]), __hadd2(rB[72+c2], rB[108+c2])), rB[144+c2]);
            hA[32 + l] = vbA;
            hB[32 + l] = vbB;
        }
        __syncwarp(0xffffffffu);
        __half2 dA = __hadd2(__hadd2(__hadd2(hA[l], hA[l+1]), __hadd2(hA[l+2], hA[l+3])), hA[l+4]);
        __half2 dB = __hadd2(__hadd2(__hadd2(hB[l], hB[l+1]), __hadd2(hB[l+2], hB[l+3])), hB[l+4]);
        unsigned bA = *reinterpret_cast<unsigned*>(&dA);
        unsigned bB = *reinterpret_cast<unsigned*>(&dB);
        unsigned k0 = ((bA & 0xFFFFu) << 10) | (gw.x & 0x3FFu);
        unsigned k1 = ((bA >> 16)    << 10) | (gw.y & 0x3FFu);
        unsigned k2 = ((bB & 0xFFFFu) << 10) | (gw.z & 0x3FFu);
        unsigned k3 = ((bB >> 16)    << 10) | (gw.w & 0x3FFu);
        if (kill123) { k1 = 0xFFFFFFFFu; k2 = 0xFFFFFFFFu; k3 = 0xFFFFFFFFu; }
        unsigned mn = umin(umin(k0, k1), umin(k2, k3));
        if (__any_sync(0xffffffffu, mn < keys[KSEL-1])) {
            ins1(k0); ins1(k1); ins1(k2); ins1(k3);
        }
    };

    const uint4* ordp = (const uint4*)g_ordw;
    auto loadg = [&](int g) -> uint4 {
        uint4 v = ordp[g];
        if (g == NGRP - 1) { v.y = v.x; v.z = v.x; v.w = v.x; }
        return v;
    };

    // this CTA handles groups g = rank, rank+4, ... (interleaved ring order)
    int ng = (NGRP - rank + NRANK - 1) / NRANK;
    uint4 w_cur = loadg(rank);
    fillG(e_sm, e_sm + 432, w_cur);
    uint4 w_nxt = (ng > 1) ? loadg(rank + NRANK) : make_uint4(0,0,0,0);

    #pragma unroll 2
    for (int i = 0; i < ng; i++) {
        int side = i & 1;
        __syncthreads();
        if (i + 1 < ng) {
            __half2* p2 = e_sm + (size_t)((side ^ 1) << 1) * 432;
            fillG(p2, p2 + 432, w_nxt);
        }
        uint4 w_n2 = (i + 2 < ng) ? loadg(rank + NRANK*(i + 2)) : make_uint4(0,0,0,0);
        __half2* pc = e_sm + (size_t)(side << 1) * 432;
        bcG(pc, pc + 432, w_cur, (rank + NRANK*i) == NGRP - 1);
        w_cur = w_nxt; w_nxt = w_n2;
    }

    size_t pix = ((size_t)t * HH + (ty0 + ly)) * WW + (tx0 + l);
    #pragma unroll
    for (int i = 0; i < KSEL; i++)
        g_keys[(size_t)(rank * KSEL + i) * NPIX + pix] = keys[i];
}

// ---------------- gather helper: compile-time range, fp16 region ----------------
template<int PB, int PE>
__device__ __forceinline__ void gather_part16(const u64* __restrict__ rpx,
                                              const float* __restrict__ w,
                                              const int* __restrict__ olin,
                                              float* __restrict__ pd, int base_px) {
    #pragma unroll
    for (int p = PB; p < PE; p++) {
        int dy = p / PSZ, dx = p - (p / PSZ) * PSZ;
        float ax = 0.f, ay = 0.f, az = 0.f;
        int bb = base_px + dy * 64 + dx;
        #pragma unroll
        for (int k = 0; k < KSEL; k++) {
            u64 n = rpx[bb + olin[k]];
            unsigned lo = (unsigned)n, hi = (unsigned)(n >> 32);
            __half2 hxy = *reinterpret_cast<__half2*>(&lo);
            __half2 hz0 = *reinterpret_cast<__half2*>(&hi);
            float2 xy = __half22float2(hxy);
            float zz = __half2float(__low2half(hz0));
            ax += w[k] * xy.x;
            ay += w[k] * xy.y;
            az += w[k] * zz;
        }
        pd[(size_t)(p * 3 + 0) * PLANE] = ax;
        pd[(size_t)(p * 3 + 1) * PLANE] = ay;
        pd[(size_t)(p * 3 + 2) * PLANE] = az;
    }
}

// ---------------- merge + softmax (once per pixel) + gather (2 threads/pixel) ----------------
__global__ void __launch_bounds__(256, 3) k_gath() {
    __shared__ u64   rpx[36*64];           // 18432 B fp16-packed region
    __shared__ float wsm[KSEL*128];        // 7168 B  per-pixel softmax weights
    __shared__ unsigned short osm[KSEL*128]; // 3584 B per-pixel neighbor offsets

    int t   = blockIdx.z;
    int ty0 = blockIdx.y * TYG;
    int tx0 = blockIdx.x * TX;
    int tid = threadIdx.x;
    int pi   = tid & 127;              // pixel index within 32x4 tile
    int half = tid >> 7;               // 0: positions 0-12, 1: positions 13-24
    int ly = pi >> 5, l = pi & 31;

    // stage region as packed fp16 (identical rounding to k_dist staging)
    const float4* xp = g_xp + (size_t)t * XPH * XPW;
    #pragma unroll
    for (int i = tid; i < 36*64; i += 256) {
        int r = i >> 6, c = i & 63;
        float4 v = xp[(size_t)(ty0 + r) * XPW + tx0 + c];
        __half2 xy = __floats2half2_rn(v.x, v.y);
        __half2 z0 = __floats2half2_rn(v.z, 0.f);
        unsigned lo = *reinterpret_cast<unsigned*>(&xy);
        unsigned hi = *reinterpret_cast<unsigned*>(&z0);
        rpx[i] = ((u64)hi << 32) | (u64)lo;
    }

    size_t pix = ((size_t)t * HH + (ty0 + ly)) * WW + (tx0 + l);

    if (half == 0) {
        // merge rank-0 list with ranks 1..3 (preload per rank, insert with early break)
        unsigned keys[KSEL];
        #pragma unroll
        for (int i = 0; i < KSEL; i++) keys[i] = g_keys[(size_t)i * NPIX + pix];
        #pragma unroll
        for (int r = 1; r < NRANK; r++) {
            unsigned rk[KSEL];
            #pragma unroll
            for (int j = 0; j < KSEL; j++) rk[j] = g_keys[(size_t)(r * KSEL + j) * NPIX + pix];
            #pragma unroll
            for (int j = 0; j < KSEL; j++) {
                unsigned k = rk[j];
                if (k >= keys[KSEL-1]) break;       // rank list sorted ascending
                #pragma unroll
                for (int s = KSEL-1; s >= 1; s--) keys[s] = umin(keys[s], umax(keys[s-1], k));
                keys[0] = umin(keys[0], k);
            }
        }

        // softmax over fp16-coded distances
        float beta = g_beta;
        __half h0 = __ushort_as_half((unsigned short)((keys[0] >> 10) & 0xFFFFu));
        float d0 = __half2float(h0);
        float w[KSEL];
        float ssum = 0.f;
        #pragma unroll
        for (int i = 0; i < KSEL; i++) {
            __half hi = __ushort_as_half((unsigned short)((keys[i] >> 10) & 0xFFFFu));
            float wi = expf(beta * (d0 - __half2float(hi)));
            w[i] = wi; ssum += wi;
        }
        float inv = 1.0f / ssum;
        #pragma unroll
        for (int i = 0; i < KSEL; i++) {
            int o  = (int)(keys[i] & 0x3FFu);
            int oyk = o / WSZ;
            int oxk = o - oyk * WSZ;
            wsm[i * 128 + pi] = w[i] * inv;
            osm[i * 128 + pi] = (unsigned short)(oyk * 64 + oxk);
        }
    }
    __syncthreads();   // region staged + wsm/osm published

    float w[KSEL];
    int   olin[KSEL];
    #pragma unroll
    for (int i = 0; i < KSEL; i++) {
        w[i]    = wsm[i * 128 + pi];
        olin[i] = osm[i * 128 + pi];
    }

    float* pd = g_pdeno + (long long)pix;
    int base_px = ly * 64 + l;
    if (half == 0) gather_part16<0, 13>(rpx, w, olin, pd, base_px);
    else           gather_part16<13, 25>(rpx, w, olin, pd, base_px);
}

// ---------------- fold + denormalize ----------------
__global__ void k_fold(float* __restrict__ out) {
    int idx = blockIdx.x * 256 + threadIdx.x;        // over t*c*H*W
    if (idx >= TCNT*CH*HH*WW) return;
    int x = idx & 127;
    int r = idx >> 7;
    int y = r & 127;
    r >>= 7;
    int c = r % 3;
    int t = r / 3;
    float s = 0.f;
    int n = 0;
    #pragma unroll
    for (int py = 0; py < PSZ; py++) {
        int yy = y + 2 - py;
        if (yy < 0 || yy > HH-1) continue;
        #pragma unroll
        for (int px = 0; px < PSZ; px++) {
            int xx = x + 2 - px;
            if (xx < 0 || xx > WW-1) continue;
            int p = (py * PSZ + px) * 3 + c;
            s += g_pdeno[(size_t)p * PLANE + ((size_t)t * HH + yy) * WW + xx];
            n++;
        }
    }
    out[idx] = 127.5f * (s / (float)n + g_mean[t*3+c] + 1.0f);
}

// ---------------- launch ----------------
extern "C" void kernel_launch(void* const* d_in, const int* in_sizes, int n_in,
                              void* d_out, int out_size) {
    const float* noisy = (const float*)d_in[0];
    const int*   sigp  = (const int*)d_in[1];
    float*       out   = (float*)d_out;

    cudaFuncSetAttribute(k_dist, cudaFuncAttributeMaxDynamicSharedMemorySize, SM_TOTAL);
    cudaFuncSetAttribute(k_dist, cudaFuncAttributePreferredSharedMemoryCarveout,
                         cudaSharedmemCarveoutMaxShared);
    cudaFuncSetAttribute(k_gath, cudaFuncAttributePreferredSharedMemoryCarveout,
                         cudaSharedmemCarveoutMaxShared);

    k_prep<<<16, 256>>>(noisy, sigp);                  // means+beta (0-11) + ring order (12-15)
    k_xp<<<(TCNT*XPH*XPW + 255)/256, 256>>>(noisy);
    dim3 gridD(NRANK * (WW/TX), HH/TY, TCNT);          // 1024 CTAs: 4 ranks per tile
    k_dist<<<gridD, 256, SM_TOTAL>>>();
    dim3 gridG(WW/TX, HH/TYG, TCNT);                   // 512 CTAs: 32x4 tiles, 2 thr/pixel
    k_gath<<<gridG, 256>>>();
    k_fold<<<(TCNT*CH*HH*WW + 255)/256, 256>>>(out);
}